// round 11
// baseline (speedup 1.0000x reference)
#include <cuda_runtime.h>
#include <cstdint>

// ============================================================================
// Stacked LSTM (H1=51, H2=1), B=2048, T=1024 (+F=64 autoregressive steps).
//
// Design: persistent recurrence, one warp per 2 batch elements (V=2).
//   - Lane j owns hidden units {j, j+32} of LSTM1 (padded: unit>=51 uses the
//     zero pad column -> its state stays exactly 0 and never contaminates).
//   - Per step: 51-term dot for 204 gates. h_k broadcast via __shfl_sync
//     (fully unrolled, immediate lane). Weights live in shared memory in a
//     transposed layout W1s[k][unit][gate] read as float4 (conflict-free).
//   - LSTM2 (hidden=1): per-lane partials + xor-butterfly reduction
//     (bit-identical result in all lanes, so the h2->input feedback in the
//     future phase is consistent without any broadcast).
//   - No cross-warp communication at any point; weights shared per block.
// ============================================================================

#define FULLMASK 0xffffffffu
#define H1 51

__device__ __forceinline__ float fsig(float x) {
    // 1 / (1 + e^-x); __expf + fast reciprocal (~2 ulp, fine vs 1e-3)
    return __fdividef(1.0f, 1.0f + __expf(-x));
}
__device__ __forceinline__ float ftanh(float x) {
    // 2 / (1 + e^-2x) - 1; saturates correctly at +-1 for large |x|
    return __fdividef(2.0f, 1.0f + __expf(-2.0f * x)) - 1.0f;
}

// W1s[k][u][g]: weight from input-slot k (h1 unit k) to gate g of unit u.
// u padded to 52; column u==51 is all zeros (lanes >=19 alias their B-slot here).
__global__ void __launch_bounds__(128, 2) lstm_seq_kernel(
    const float* __restrict__ input,   // [B, T]
    const float* __restrict__ Wih1,    // [204, 1]
    const float* __restrict__ Whh1,    // [204, 51]
    const float* __restrict__ bih1,    // [204]
    const float* __restrict__ bhh1,    // [204]
    const float* __restrict__ Wih2,    // [4, 51]
    const float* __restrict__ Whh2,    // [4, 1]
    const float* __restrict__ bih2,    // [4]
    const float* __restrict__ bhh2,    // [4]
    float* __restrict__ out,           // [B, T+F]
    int T, int TF)
{
    __shared__ float4 W1s[H1 * 52];    // 51*52*16 = 42432 B

    const int tid = threadIdx.x;

    // ---- transpose Whh1 [gate*51+u][k] -> W1s[k*52+u] (float4 over gates) ----
    for (int idx = tid; idx < H1 * 52; idx += blockDim.x) {
        int k = idx / 52, u = idx % 52;
        float4 w = make_float4(0.f, 0.f, 0.f, 0.f);
        if (u < H1) {
            w.x = Whh1[(0 * H1 + u) * H1 + k];
            w.y = Whh1[(1 * H1 + u) * H1 + k];
            w.z = Whh1[(2 * H1 + u) * H1 + k];
            w.w = Whh1[(3 * H1 + u) * H1 + k];
        }
        W1s[idx] = w;
    }
    __syncthreads();

    const int lane   = tid & 31;
    const int warp   = blockIdx.x * (blockDim.x >> 5) + (tid >> 5);
    const int b0     = warp * 2;
    const int b1     = warp * 2 + 1;

    const int  uA    = lane;
    const bool hasB  = (lane + 32) < H1;           // lanes 0..18
    const int  uB    = hasB ? (lane + 32) : H1;    // zero pad column for 19..31
    const int  uBw   = hasB ? (lane + 32) : 0;     // safe gmem index (weights zeroed below)

    // ---- per-lane register weights ----
    float WiA[4], WiB[4], bA[4], bB[4], W2A[4], W2B[4], W2h[4], b2[4];
#pragma unroll
    for (int g = 0; g < 4; g++) {
        WiA[g] = Wih1[g * H1 + uA];
        bA[g]  = bih1[g * H1 + uA] + bhh1[g * H1 + uA];
        W2A[g] = Wih2[g * H1 + uA];
        float wib = Wih1[g * H1 + uBw];
        float bb  = bih1[g * H1 + uBw] + bhh1[g * H1 + uBw];
        float w2b = Wih2[g * H1 + uBw];
        WiB[g] = hasB ? wib : 0.f;
        bB[g]  = hasB ? bb  : 0.f;
        W2B[g] = hasB ? w2b : 0.f;
        W2h[g] = Whh2[g];
        b2[g]  = bih2[g] + bhh2[g];
    }

    // ---- state (2 batch elements per warp) ----
    float hA0 = 0.f, hA1 = 0.f, hB0 = 0.f, hB1 = 0.f;
    float cA0 = 0.f, cA1 = 0.f, cB0 = 0.f, cB1 = 0.f;
    float h20 = 0.f, h21 = 0.f, c20 = 0.f, c21 = 0.f;

    const float* in0p = input + (size_t)b0 * T;
    const float* in1p = input + (size_t)b1 * T;
    float* out0 = out + (size_t)b0 * TF;
    float* out1 = out + (size_t)b1 * TF;

#pragma unroll 1
    for (int t = 0; t < TF; t++) {
        // LSTM1 input: data during main phase, own h2 during future phase
        float x0, x1;
        if (t < T) {
            x0 = __ldg(in0p + t);
            x1 = __ldg(in1p + t);
        } else {
            x0 = h20;
            x1 = h21;
        }

        // ---- LSTM1 gate accumulators: bias + x*Wih ----
        float aA0[4], aA1[4], aB0[4], aB1[4];
#pragma unroll
        for (int g = 0; g < 4; g++) {
            aA0[g] = fmaf(x0, WiA[g], bA[g]);
            aA1[g] = fmaf(x1, WiA[g], bA[g]);
            aB0[g] = fmaf(x0, WiB[g], bB[g]);
            aB1[g] = fmaf(x1, WiB[g], bB[g]);
        }

        // ---- 51-term recurrent dot (fully unrolled, shfl broadcast of h_k) ----
#pragma unroll
        for (int k = 0; k < H1; k++) {
            float s0  = (k < 32) ? hA0 : hB0;
            float s1  = (k < 32) ? hA1 : hB1;
            float hk0 = __shfl_sync(FULLMASK, s0, k & 31);
            float hk1 = __shfl_sync(FULLMASK, s1, k & 31);
            float4 wA = W1s[k * 52 + uA];
            float4 wB = W1s[k * 52 + uB];
            aA0[0] = fmaf(hk0, wA.x, aA0[0]);
            aA0[1] = fmaf(hk0, wA.y, aA0[1]);
            aA0[2] = fmaf(hk0, wA.z, aA0[2]);
            aA0[3] = fmaf(hk0, wA.w, aA0[3]);
            aA1[0] = fmaf(hk1, wA.x, aA1[0]);
            aA1[1] = fmaf(hk1, wA.y, aA1[1]);
            aA1[2] = fmaf(hk1, wA.z, aA1[2]);
            aA1[3] = fmaf(hk1, wA.w, aA1[3]);
            aB0[0] = fmaf(hk0, wB.x, aB0[0]);
            aB0[1] = fmaf(hk0, wB.y, aB0[1]);
            aB0[2] = fmaf(hk0, wB.z, aB0[2]);
            aB0[3] = fmaf(hk0, wB.w, aB0[3]);
            aB1[0] = fmaf(hk1, wB.x, aB1[0]);
            aB1[1] = fmaf(hk1, wB.y, aB1[1]);
            aB1[2] = fmaf(hk1, wB.z, aB1[2]);
            aB1[3] = fmaf(hk1, wB.w, aB1[3]);
        }

        // ---- LSTM1 activations + state update (i,f,g,o) ----
        {
            float i = fsig(aA0[0]), f = fsig(aA0[1]), g = ftanh(aA0[2]), o = fsig(aA0[3]);
            cA0 = f * cA0 + i * g;
            hA0 = o * ftanh(cA0);
        }
        {
            float i = fsig(aA1[0]), f = fsig(aA1[1]), g = ftanh(aA1[2]), o = fsig(aA1[3]);
            cA1 = f * cA1 + i * g;
            hA1 = o * ftanh(cA1);
        }
        {
            float i = fsig(aB0[0]), f = fsig(aB0[1]), g = ftanh(aB0[2]), o = fsig(aB0[3]);
            cB0 = f * cB0 + i * g;
            hB0 = o * ftanh(cB0);
        }
        {
            float i = fsig(aB1[0]), f = fsig(aB1[1]), g = ftanh(aB1[2]), o = fsig(aB1[3]);
            cB1 = f * cB1 + i * g;
            hB1 = o * ftanh(cB1);
        }

        // ---- LSTM2: per-lane partials, xor-butterfly reduce (bit-identical) ----
        float p0_0 = hA0 * W2A[0] + hB0 * W2B[0];
        float p1_0 = hA0 * W2A[1] + hB0 * W2B[1];
        float p2_0 = hA0 * W2A[2] + hB0 * W2B[2];
        float p3_0 = hA0 * W2A[3] + hB0 * W2B[3];
        float p0_1 = hA1 * W2A[0] + hB1 * W2B[0];
        float p1_1 = hA1 * W2A[1] + hB1 * W2B[1];
        float p2_1 = hA1 * W2A[2] + hB1 * W2B[2];
        float p3_1 = hA1 * W2A[3] + hB1 * W2B[3];
#pragma unroll
        for (int off = 16; off >= 1; off >>= 1) {
            p0_0 += __shfl_xor_sync(FULLMASK, p0_0, off);
            p1_0 += __shfl_xor_sync(FULLMASK, p1_0, off);
            p2_0 += __shfl_xor_sync(FULLMASK, p2_0, off);
            p3_0 += __shfl_xor_sync(FULLMASK, p3_0, off);
            p0_1 += __shfl_xor_sync(FULLMASK, p0_1, off);
            p1_1 += __shfl_xor_sync(FULLMASK, p1_1, off);
            p2_1 += __shfl_xor_sync(FULLMASK, p2_1, off);
            p3_1 += __shfl_xor_sync(FULLMASK, p3_1, off);
        }
        {
            float i2 = fsig (p0_0 + W2h[0] * h20 + b2[0]);
            float f2 = fsig (p1_0 + W2h[1] * h20 + b2[1]);
            float g2 = ftanh(p2_0 + W2h[2] * h20 + b2[2]);
            float o2 = fsig (p3_0 + W2h[3] * h20 + b2[3]);
            c20 = f2 * c20 + i2 * g2;
            h20 = o2 * ftanh(c20);
        }
        {
            float i2 = fsig (p0_1 + W2h[0] * h21 + b2[0]);
            float f2 = fsig (p1_1 + W2h[1] * h21 + b2[1]);
            float g2 = ftanh(p2_1 + W2h[2] * h21 + b2[2]);
            float o2 = fsig (p3_1 + W2h[3] * h21 + b2[3]);
            c21 = f2 * c21 + i2 * g2;
            h21 = o2 * ftanh(c21);
        }

        if (lane == 0) {
            out0[t] = h20;
            out1[t] = h21;
        }
    }
}

extern "C" void kernel_launch(void* const* d_in, const int* in_sizes, int n_in,
                              void* d_out, int out_size) {
    const float* input = (const float*)d_in[0];
    const float* Wih1  = (const float*)d_in[1];
    const float* Whh1  = (const float*)d_in[2];
    const float* bih1  = (const float*)d_in[3];
    const float* bhh1  = (const float*)d_in[4];
    const float* Wih2  = (const float*)d_in[5];
    const float* Whh2  = (const float*)d_in[6];
    const float* bih2  = (const float*)d_in[7];
    const float* bhh2  = (const float*)d_in[8];
    float* out = (float*)d_out;

    const int B  = 2048;
    const int T  = in_sizes[0] / B;     // 1024
    const int TF = out_size / B;        // 1088

    // 4 warps/block, 2 batch elements/warp -> 8 batch/block -> 256 blocks
    const int threads = 128;
    const int blocks  = B / 8;
    lstm_seq_kernel<<<blocks, threads>>>(input, Wih1, Whh1, bih1, bhh1,
                                         Wih2, Whh2, bih2, bhh2,
                                         out, T, TF);
}

// round 12
// speedup vs baseline: 1.0953x; 1.0953x over previous
#include <cuda_runtime.h>
#include <cstdint>

// ============================================================================
// Stacked LSTM (H1=51, H2=1), B=2048, T=1024 (+F=64 autoregressive steps).
//
// Round 11: V=4 batch elements per warp + packed fma.rn.f32x2 over gate pairs.
//   - Weight LDS.128 per step amortized over 4 batch elements (2x less smem
//     crossbar traffic per element vs V=2). The float4 weight load IS two
//     aligned f32x2 operands -> zero repack cost for FFMA2.
//   - FFMA2 halves the fma-pipe instruction count (bit-identical fp32 math).
//   - h_k broadcast via __shfl_sync + one mov.b64 dup (ALU pipe, off the
//     critical smem pipe).
//   - LSTM2 (hidden=1): xor-butterfly reduction, bit-identical in all lanes
//     so the autoregressive h2 feedback needs no broadcast.
// ============================================================================

#define FULLMASK 0xffffffffu
#define H1 51

typedef unsigned long long ull;

#define FMA2(d, a, b, c) \
    asm("fma.rn.f32x2 %0, %1, %2, %3;" : "=l"(d) : "l"(a), "l"(b), "l"(c))

__device__ __forceinline__ ull pack2(float lo, float hi) {
    ull r; asm("mov.b64 %0, {%1, %2};" : "=l"(r) : "f"(lo), "f"(hi)); return r;
}
__device__ __forceinline__ ull dup2(float x) {
    ull r; asm("mov.b64 %0, {%1, %1};" : "=l"(r) : "f"(x)); return r;
}
__device__ __forceinline__ float2 unpack2(ull v) {
    float2 r; asm("mov.b64 {%0, %1}, %2;" : "=f"(r.x), "=f"(r.y) : "l"(v)); return r;
}

__device__ __forceinline__ float fsig(float x) {
    return __fdividef(1.0f, 1.0f + __expf(-x));
}
__device__ __forceinline__ float ftanh(float x) {
    return __fdividef(2.0f, 1.0f + __expf(-2.0f * x)) - 1.0f;
}

// W1s[k][u] = float4 of gate weights (i,f,g,o) from h1-unit k to unit u.
// u padded to 52; column u==51 is zeros (pad slot for lanes 19..31).
__global__ void __launch_bounds__(64, 1) lstm_seq_kernel(
    const float* __restrict__ input,   // [B, T]
    const float* __restrict__ Wih1,    // [204, 1]
    const float* __restrict__ Whh1,    // [204, 51]
    const float* __restrict__ bih1,    // [204]
    const float* __restrict__ bhh1,    // [204]
    const float* __restrict__ Wih2,    // [4, 51]
    const float* __restrict__ Whh2,    // [4, 1]
    const float* __restrict__ bih2,    // [4]
    const float* __restrict__ bhh2,    // [4]
    float* __restrict__ out,           // [B, T+F]
    int T, int TF)
{
    __shared__ float4 W1s[H1 * 52];    // 42432 B (< 48KB static limit)

    const int tid = threadIdx.x;

    // ---- transpose Whh1 [gate*51+u][k] -> W1s[k*52+u] (float4 over gates) ----
    for (int idx = tid; idx < H1 * 52; idx += blockDim.x) {
        int k = idx / 52, u = idx % 52;
        float4 w = make_float4(0.f, 0.f, 0.f, 0.f);
        if (u < H1) {
            w.x = Whh1[(0 * H1 + u) * H1 + k];
            w.y = Whh1[(1 * H1 + u) * H1 + k];
            w.z = Whh1[(2 * H1 + u) * H1 + k];
            w.w = Whh1[(3 * H1 + u) * H1 + k];
        }
        W1s[idx] = w;
    }
    __syncthreads();

    const ulonglong2* __restrict__ W1u =
        reinterpret_cast<const ulonglong2*>(W1s);

    const int lane = tid & 31;
    const int warp = blockIdx.x * (blockDim.x >> 5) + (tid >> 5);

    const int  uA   = lane;
    const bool hasB = (lane + 32) < H1;          // lanes 0..18
    const int  uB   = hasB ? (lane + 32) : H1;   // pad column for 19..31
    const int  uBw  = hasB ? (lane + 32) : 0;    // safe gmem index

    // ---- per-lane constants, packed over gate pairs (i,f) / (g,o) ----
    float WiA[4], WiB[4], bA[4], bB[4], W2A[4], W2B[4], W2h[4], b2[4];
#pragma unroll
    for (int g = 0; g < 4; g++) {
        WiA[g] = Wih1[g * H1 + uA];
        bA[g]  = bih1[g * H1 + uA] + bhh1[g * H1 + uA];
        W2A[g] = Wih2[g * H1 + uA];
        float wib = Wih1[g * H1 + uBw];
        float bb  = bih1[g * H1 + uBw] + bhh1[g * H1 + uBw];
        float w2b = Wih2[g * H1 + uBw];
        WiB[g] = hasB ? wib : 0.f;
        bB[g]  = hasB ? bb  : 0.f;
        W2B[g] = hasB ? w2b : 0.f;
        W2h[g] = Whh2[g];
        b2[g]  = bih2[g] + bhh2[g];
    }
    const ull WiAp0 = pack2(WiA[0], WiA[1]), WiAp1 = pack2(WiA[2], WiA[3]);
    const ull WiBp0 = pack2(WiB[0], WiB[1]), WiBp1 = pack2(WiB[2], WiB[3]);
    const ull bAp0  = pack2(bA[0],  bA[1]),  bAp1  = pack2(bA[2],  bA[3]);
    const ull bBp0  = pack2(bB[0],  bB[1]),  bBp1  = pack2(bB[2],  bB[3]);

    // ---- state: 4 batch elements per warp ----
    float hA[4] = {0.f, 0.f, 0.f, 0.f};
    float hB[4] = {0.f, 0.f, 0.f, 0.f};
    float cA[4] = {0.f, 0.f, 0.f, 0.f};
    float cB[4] = {0.f, 0.f, 0.f, 0.f};
    float h2[4] = {0.f, 0.f, 0.f, 0.f};
    float c2[4] = {0.f, 0.f, 0.f, 0.f};

    const float* inp[4];
    float*       outp[4];
#pragma unroll
    for (int e = 0; e < 4; e++) {
        int b = warp * 4 + e;
        inp[e]  = input + (size_t)b * T;
        outp[e] = out   + (size_t)b * TF;
    }

#pragma unroll 1
    for (int t = 0; t < TF; t++) {
        // LSTM1 input: data in main phase, own h2 in future phase
        float x[4];
        if (t < T) {
#pragma unroll
            for (int e = 0; e < 4; e++) x[e] = __ldg(inp[e] + t);
        } else {
#pragma unroll
            for (int e = 0; e < 4; e++) x[e] = h2[e];
        }

        // ---- gate accumulators (packed pairs): bias + x*Wih ----
        ull aA0[4], aA1[4], aB0[4], aB1[4];   // [elem], pair0=(i,f) pair1=(g,o)
#pragma unroll
        for (int e = 0; e < 4; e++) {
            ull d = dup2(x[e]);
            FMA2(aA0[e], d, WiAp0, bAp0);
            FMA2(aA1[e], d, WiAp1, bAp1);
            FMA2(aB0[e], d, WiBp0, bBp0);
            FMA2(aB1[e], d, WiBp1, bBp1);
        }

        // ---- 51-term recurrent dot (unrolled, shfl bcast, FFMA2) ----
#pragma unroll
        for (int k = 0; k < H1; k++) {
            float hk[4];
#pragma unroll
            for (int e = 0; e < 4; e++) {
                float s = (k < 32) ? hA[e] : hB[e];
                hk[e] = __shfl_sync(FULLMASK, s, k & 31);
            }
            ulonglong2 wA = W1u[k * 52 + uA];
            ulonglong2 wB = W1u[k * 52 + uB];
#pragma unroll
            for (int e = 0; e < 4; e++) {
                ull d = dup2(hk[e]);
                FMA2(aA0[e], d, wA.x, aA0[e]);
                FMA2(aA1[e], d, wA.y, aA1[e]);
                FMA2(aB0[e], d, wB.x, aB0[e]);
                FMA2(aB1[e], d, wB.y, aB1[e]);
            }
        }

        // ---- LSTM1 activations + state update, then LSTM2 partials ----
        float p[4][4];   // [elem][gate] LSTM2 partial sums
#pragma unroll
        for (int e = 0; e < 4; e++) {
            float2 vA0 = unpack2(aA0[e]), vA1 = unpack2(aA1[e]);
            float2 vB0 = unpack2(aB0[e]), vB1 = unpack2(aB1[e]);
            {
                float i = fsig(vA0.x), f = fsig(vA0.y);
                float g = ftanh(vA1.x), o = fsig(vA1.y);
                cA[e] = f * cA[e] + i * g;
                hA[e] = o * ftanh(cA[e]);
            }
            {
                float i = fsig(vB0.x), f = fsig(vB0.y);
                float g = ftanh(vB1.x), o = fsig(vB1.y);
                cB[e] = f * cB[e] + i * g;
                hB[e] = o * ftanh(cB[e]);
            }
#pragma unroll
            for (int g = 0; g < 4; g++)
                p[e][g] = fmaf(hA[e], W2A[g], hB[e] * W2B[g]);
        }

        // ---- butterfly reduce 16 partials (bit-identical in all lanes) ----
#pragma unroll
        for (int off = 16; off >= 1; off >>= 1) {
#pragma unroll
            for (int e = 0; e < 4; e++) {
#pragma unroll
                for (int g = 0; g < 4; g++)
                    p[e][g] += __shfl_xor_sync(FULLMASK, p[e][g], off);
            }
        }

        // ---- LSTM2 cell update + output ----
#pragma unroll
        for (int e = 0; e < 4; e++) {
            float i2 = fsig (p[e][0] + W2h[0] * h2[e] + b2[0]);
            float f2 = fsig (p[e][1] + W2h[1] * h2[e] + b2[1]);
            float g2 = ftanh(p[e][2] + W2h[2] * h2[e] + b2[2]);
            float o2 = fsig (p[e][3] + W2h[3] * h2[e] + b2[3]);
            c2[e] = f2 * c2[e] + i2 * g2;
            h2[e] = o2 * ftanh(c2[e]);
        }
        if (lane == 0) {
#pragma unroll
            for (int e = 0; e < 4; e++) outp[e][t] = h2[e];
        }
    }
}

extern "C" void kernel_launch(void* const* d_in, const int* in_sizes, int n_in,
                              void* d_out, int out_size) {
    const float* input = (const float*)d_in[0];
    const float* Wih1  = (const float*)d_in[1];
    const float* Whh1  = (const float*)d_in[2];
    const float* bih1  = (const float*)d_in[3];
    const float* bhh1  = (const float*)d_in[4];
    const float* Wih2  = (const float*)d_in[5];
    const float* Whh2  = (const float*)d_in[6];
    const float* bih2  = (const float*)d_in[7];
    const float* bhh2  = (const float*)d_in[8];
    float* out = (float*)d_out;

    const int B  = 2048;
    const int T  = in_sizes[0] / B;     // 1024
    const int TF = out_size / B;        // 1088

    // 2 warps/block, 4 batch elements/warp -> 8 batch/block -> 256 blocks
    const int threads = 64;
    const int blocks  = B / 8;
    lstm_seq_kernel<<<blocks, threads>>>(input, Wih1, Whh1, bih1, bhh1,
                                         Wih2, Whh2, bih2, bhh2,
                                         out, T, TF);
}

// round 13
// speedup vs baseline: 1.2496x; 1.1409x over previous
#include <cuda_runtime.h>
#include <cstdint>

// ============================================================================
// Stacked LSTM (H1=51, H2=1), B=2048, T=1024 (+F=64 autoregressive steps).
//
// Round 13: tanh.approx activations + one-step-deferred LSTM2.
//   - V=4 batch elements per warp, FFMA2 packed gate pairs (as round 12).
//   - All activations via MUFU.TANH (1 op): tanh direct,
//     sigmoid(x) = 0.5*tanh(0.5x)+0.5. Halves MUFU pressure and chains.
//   - LSTM2 (butterfly + cell update) for step t-1 executes at the top of
//     iteration t: independent of iteration t's k-loop in the main phase, so
//     its shfl/MUFU latency hides under the FFMA2 stream. In the future
//     phase this ordering is exactly the h2->x dependency.
// ============================================================================

#define FULLMASK 0xffffffffu
#define H1 51

typedef unsigned long long ull;

#define FMA2(d, a, b, c) \
    asm("fma.rn.f32x2 %0, %1, %2, %3;" : "=l"(d) : "l"(a), "l"(b), "l"(c))

__device__ __forceinline__ ull pack2(float lo, float hi) {
    ull r; asm("mov.b64 %0, {%1, %2};" : "=l"(r) : "f"(lo), "f"(hi)); return r;
}
__device__ __forceinline__ ull dup2(float x) {
    ull r; asm("mov.b64 %0, {%1, %1};" : "=l"(r) : "f"(x)); return r;
}
__device__ __forceinline__ float2 unpack2(ull v) {
    float2 r; asm("mov.b64 {%0, %1}, %2;" : "=f"(r.x), "=f"(r.y) : "l"(v)); return r;
}

__device__ __forceinline__ float ftanh(float x) {
    float r; asm("tanh.approx.f32 %0, %1;" : "=f"(r) : "f"(x)); return r;
}
__device__ __forceinline__ float fsig(float x) {
    return fmaf(0.5f, ftanh(0.5f * x), 0.5f);
}

// W1s[k][u] = float4 of gate weights (i,f,g,o) from h1-unit k to unit u.
// u padded to 52; column u==51 is zeros (pad slot for lanes 19..31).
__global__ void __launch_bounds__(64, 1) lstm_seq_kernel(
    const float* __restrict__ input,   // [B, T]
    const float* __restrict__ Wih1,    // [204, 1]
    const float* __restrict__ Whh1,    // [204, 51]
    const float* __restrict__ bih1,    // [204]
    const float* __restrict__ bhh1,    // [204]
    const float* __restrict__ Wih2,    // [4, 51]
    const float* __restrict__ Whh2,    // [4, 1]
    const float* __restrict__ bih2,    // [4]
    const float* __restrict__ bhh2,    // [4]
    float* __restrict__ out,           // [B, T+F]
    int T, int TF)
{
    __shared__ float4 W1s[H1 * 52];    // 42432 B

    const int tid = threadIdx.x;

    // ---- transpose Whh1 [gate*51+u][k] -> W1s[k*52+u] (float4 over gates) ----
    for (int idx = tid; idx < H1 * 52; idx += blockDim.x) {
        int k = idx / 52, u = idx % 52;
        float4 w = make_float4(0.f, 0.f, 0.f, 0.f);
        if (u < H1) {
            w.x = Whh1[(0 * H1 + u) * H1 + k];
            w.y = Whh1[(1 * H1 + u) * H1 + k];
            w.z = Whh1[(2 * H1 + u) * H1 + k];
            w.w = Whh1[(3 * H1 + u) * H1 + k];
        }
        W1s[idx] = w;
    }
    __syncthreads();

    const ulonglong2* __restrict__ W1u =
        reinterpret_cast<const ulonglong2*>(W1s);

    const int lane = tid & 31;
    const int warp = blockIdx.x * (blockDim.x >> 5) + (tid >> 5);

    const int  uA   = lane;
    const bool hasB = (lane + 32) < H1;          // lanes 0..18
    const int  uB   = hasB ? (lane + 32) : H1;   // pad column for 19..31
    const int  uBw  = hasB ? (lane + 32) : 0;    // safe gmem index

    // ---- per-lane constants, packed over gate pairs (i,f) / (g,o) ----
    float WiA[4], WiB[4], bA[4], bB[4], W2A[4], W2B[4], W2h[4], b2[4];
#pragma unroll
    for (int g = 0; g < 4; g++) {
        WiA[g] = Wih1[g * H1 + uA];
        bA[g]  = bih1[g * H1 + uA] + bhh1[g * H1 + uA];
        W2A[g] = Wih2[g * H1 + uA];
        float wib = Wih1[g * H1 + uBw];
        float bb  = bih1[g * H1 + uBw] + bhh1[g * H1 + uBw];
        float w2b = Wih2[g * H1 + uBw];
        WiB[g] = hasB ? wib : 0.f;
        bB[g]  = hasB ? bb  : 0.f;
        W2B[g] = hasB ? w2b : 0.f;
        W2h[g] = Whh2[g];
        b2[g]  = bih2[g] + bhh2[g];
    }
    const ull WiAp0 = pack2(WiA[0], WiA[1]), WiAp1 = pack2(WiA[2], WiA[3]);
    const ull WiBp0 = pack2(WiB[0], WiB[1]), WiBp1 = pack2(WiB[2], WiB[3]);
    const ull bAp0  = pack2(bA[0],  bA[1]),  bAp1  = pack2(bA[2],  bA[3]);
    const ull bBp0  = pack2(bB[0],  bB[1]),  bBp1  = pack2(bB[2],  bB[3]);

    // ---- state: 4 batch elements per warp ----
    float hA[4] = {0.f, 0.f, 0.f, 0.f};
    float hB[4] = {0.f, 0.f, 0.f, 0.f};
    float cA[4] = {0.f, 0.f, 0.f, 0.f};
    float cB[4] = {0.f, 0.f, 0.f, 0.f};
    float h2[4] = {0.f, 0.f, 0.f, 0.f};
    float c2[4] = {0.f, 0.f, 0.f, 0.f};
    float p[4][4];                      // deferred LSTM2 partials (step t-1)

    const float* inp[4];
    float*       outp[4];
#pragma unroll
    for (int e = 0; e < 4; e++) {
        int b = warp * 4 + e;
        inp[e]  = input + (size_t)b * T;
        outp[e] = out   + (size_t)b * TF;
    }

#pragma unroll 1
    for (int t = 0; t < TF; t++) {
        // ---- finish step t-1's LSTM2 (butterfly + cell + output write).
        //      Main phase: independent of this iteration's k-loop -> overlaps.
        //      Future phase: produces the h2 this iteration consumes as x. ----
        if (t > 0) {
#pragma unroll
            for (int off = 16; off >= 1; off >>= 1) {
#pragma unroll
                for (int e = 0; e < 4; e++) {
#pragma unroll
                    for (int g = 0; g < 4; g++)
                        p[e][g] += __shfl_xor_sync(FULLMASK, p[e][g], off);
                }
            }
#pragma unroll
            for (int e = 0; e < 4; e++) {
                float i2 = fsig (p[e][0] + W2h[0] * h2[e] + b2[0]);
                float f2 = fsig (p[e][1] + W2h[1] * h2[e] + b2[1]);
                float g2 = ftanh(p[e][2] + W2h[2] * h2[e] + b2[2]);
                float o2 = fsig (p[e][3] + W2h[3] * h2[e] + b2[3]);
                c2[e] = f2 * c2[e] + i2 * g2;
                h2[e] = o2 * ftanh(c2[e]);
            }
            if (lane == 0) {
#pragma unroll
                for (int e = 0; e < 4; e++) outp[e][t - 1] = h2[e];
            }
        }

        // ---- LSTM1 input: data in main phase, own h2 in future phase ----
        float x[4];
        if (t < T) {
#pragma unroll
            for (int e = 0; e < 4; e++) x[e] = __ldg(inp[e] + t);
        } else {
#pragma unroll
            for (int e = 0; e < 4; e++) x[e] = h2[e];
        }

        // ---- gate accumulators (packed pairs): bias + x*Wih ----
        ull aA0[4], aA1[4], aB0[4], aB1[4];   // [elem], pair0=(i,f) pair1=(g,o)
#pragma unroll
        for (int e = 0; e < 4; e++) {
            ull d = dup2(x[e]);
            FMA2(aA0[e], d, WiAp0, bAp0);
            FMA2(aA1[e], d, WiAp1, bAp1);
            FMA2(aB0[e], d, WiBp0, bBp0);
            FMA2(aB1[e], d, WiBp1, bBp1);
        }

        // ---- 51-term recurrent dot (unrolled, shfl bcast, FFMA2) ----
#pragma unroll
        for (int k = 0; k < H1; k++) {
            float hk[4];
#pragma unroll
            for (int e = 0; e < 4; e++) {
                float s = (k < 32) ? hA[e] : hB[e];
                hk[e] = __shfl_sync(FULLMASK, s, k & 31);
            }
            ulonglong2 wA = W1u[k * 52 + uA];
            ulonglong2 wB = W1u[k * 52 + uB];
#pragma unroll
            for (int e = 0; e < 4; e++) {
                ull d = dup2(hk[e]);
                FMA2(aA0[e], d, wA.x, aA0[e]);
                FMA2(aA1[e], d, wA.y, aA1[e]);
                FMA2(aB0[e], d, wB.x, aB0[e]);
                FMA2(aB1[e], d, wB.y, aB1[e]);
            }
        }

        // ---- LSTM1 activations + state update, stash LSTM2 partials ----
#pragma unroll
        for (int e = 0; e < 4; e++) {
            float2 vA0 = unpack2(aA0[e]), vA1 = unpack2(aA1[e]);
            float2 vB0 = unpack2(aB0[e]), vB1 = unpack2(aB1[e]);
            {
                float i = fsig(vA0.x), f = fsig(vA0.y);
                float g = ftanh(vA1.x), o = fsig(vA1.y);
                cA[e] = f * cA[e] + i * g;
                hA[e] = o * ftanh(cA[e]);
            }
            {
                float i = fsig(vB0.x), f = fsig(vB0.y);
                float g = ftanh(vB1.x), o = fsig(vB1.y);
                cB[e] = f * cB[e] + i * g;
                hB[e] = o * ftanh(cB[e]);
            }
#pragma unroll
            for (int g = 0; g < 4; g++)
                p[e][g] = fmaf(hA[e], W2A[g], hB[e] * W2B[g]);
        }
    }

    // ---- epilogue: finish step TF-1's LSTM2 ----
#pragma unroll
    for (int off = 16; off >= 1; off >>= 1) {
#pragma unroll
        for (int e = 0; e < 4; e++) {
#pragma unroll
            for (int g = 0; g < 4; g++)
                p[e][g] += __shfl_xor_sync(FULLMASK, p[e][g], off);
        }
    }
#pragma unroll
    for (int e = 0; e < 4; e++) {
        float i2 = fsig (p[e][0] + W2h[0] * h2[e] + b2[0]);
        float f2 = fsig (p[e][1] + W2h[1] * h2[e] + b2[1]);
        float g2 = ftanh(p[e][2] + W2h[2] * h2[e] + b2[2]);
        float o2 = fsig (p[e][3] + W2h[3] * h2[e] + b2[3]);
        c2[e] = f2 * c2[e] + i2 * g2;
        h2[e] = o2 * ftanh(c2[e]);
    }
    if (lane == 0) {
#pragma unroll
        for (int e = 0; e < 4; e++) outp[e][TF - 1] = h2[e];
    }
}

extern "C" void kernel_launch(void* const* d_in, const int* in_sizes, int n_in,
                              void* d_out, int out_size) {
    const float* input = (const float*)d_in[0];
    const float* Wih1  = (const float*)d_in[1];
    const float* Whh1  = (const float*)d_in[2];
    const float* bih1  = (const float*)d_in[3];
    const float* bhh1  = (const float*)d_in[4];
    const float* Wih2  = (const float*)d_in[5];
    const float* Whh2  = (const float*)d_in[6];
    const float* bih2  = (const float*)d_in[7];
    const float* bhh2  = (const float*)d_in[8];
    float* out = (float*)d_out;

    const int B  = 2048;
    const int T  = in_sizes[0] / B;     // 1024
    const int TF = out_size / B;        // 1088

    // 2 warps/block, 4 batch elements/warp -> 8 batch/block -> 256 blocks
    const int threads = 64;
    const int blocks  = B / 8;
    lstm_seq_kernel<<<blocks, threads>>>(input, Wih1, Whh1, bih1, bhh1,
                                         Wih2, Whh2, bih2, bhh2,
                                         out, T, TF);
}

// round 14
// speedup vs baseline: 1.5398x; 1.2322x over previous
#include <cuda_runtime.h>
#include <cstdint>

// ============================================================================
// Stacked LSTM (H1=51, H2=1), B=2048, T=1024 (+F=64 autoregressive steps).
//
// Round 14: kill the shuffle traffic on the smem crossbar.
//   - h1 lives in shared memory per step (8 STS); the k-loop broadcast reads
//     it in float4 chunks: 1 crossbar cycle per 4 k-values (vs 4 shfl).
//   - LSTM2: lane (e,g) computes the full 51-dot from smem (broadcast,
//     conflict-free), 4 shfls gather gates. No 80-shfl butterfly.
//   - V=4 elems/warp, fp32 weights, FFMA2 packed gate pairs, tanh.approx,
//     one-step-deferred LSTM2 (overlaps the k-loop in the main phase).
//   - W1s extended to 52 zero rows so the k-loop runs uniform 13x4 chunks.
// ============================================================================

#define FULLMASK 0xffffffffu
#define H1 51
#define KP 52

typedef unsigned long long ull;

#define FMA2(d, a, b, c) \
    asm("fma.rn.f32x2 %0, %1, %2, %3;" : "=l"(d) : "l"(a), "l"(b), "l"(c))

__device__ __forceinline__ ull pack2(float lo, float hi) {
    ull r; asm("mov.b64 %0, {%1, %2};" : "=l"(r) : "f"(lo), "f"(hi)); return r;
}
__device__ __forceinline__ ull dup2(float x) {
    ull r; asm("mov.b64 %0, {%1, %1};" : "=l"(r) : "f"(x)); return r;
}
__device__ __forceinline__ float2 unpack2(ull v) {
    float2 r; asm("mov.b64 {%0, %1}, %2;" : "=f"(r.x), "=f"(r.y) : "l"(v)); return r;
}

__device__ __forceinline__ float ftanh(float x) {
    float r; asm("tanh.approx.f32 %0, %1;" : "=f"(r) : "f"(x)); return r;
}
__device__ __forceinline__ float fsig(float x) {
    return fmaf(0.5f, ftanh(0.5f * x), 0.5f);
}

__global__ void __launch_bounds__(64, 1) lstm_seq_kernel(
    const float* __restrict__ input,   // [B, T]
    const float* __restrict__ Wih1,    // [204, 1]
    const float* __restrict__ Whh1,    // [204, 51]
    const float* __restrict__ bih1,    // [204]
    const float* __restrict__ bhh1,    // [204]
    const float* __restrict__ Wih2,    // [4, 51]
    const float* __restrict__ Whh2,    // [4, 1]
    const float* __restrict__ bih2,    // [4]
    const float* __restrict__ bhh2,    // [4]
    float* __restrict__ out,           // [B, T+F]
    int T, int TF)
{
    // W1s[k][u]: float4 gate weights (i,f,g,o) from h1-unit k to unit u.
    // 52 rows x 52 cols; row 51 and col 51 are zeros (pad).
    __shared__ float4 W1s[KP * KP];        // 43264 B
    __shared__ float4 W2s[4 * 13];         // Wih2[g][k] in 13 float4 chunks
    __shared__ float4 Hs[2][4][13];        // [warpInBlk][elem][chunk] h1 state

    const int tid = threadIdx.x;

    // ---- init shared: transposed Whh1, chunked Wih2, zeroed Hs ----
    for (int idx = tid; idx < KP * KP; idx += blockDim.x) {
        int k = idx / KP, u = idx % KP;
        float4 w = make_float4(0.f, 0.f, 0.f, 0.f);
        if (k < H1 && u < H1) {
            w.x = Whh1[(0 * H1 + u) * H1 + k];
            w.y = Whh1[(1 * H1 + u) * H1 + k];
            w.z = Whh1[(2 * H1 + u) * H1 + k];
            w.w = Whh1[(3 * H1 + u) * H1 + k];
        }
        W1s[idx] = w;
    }
    for (int idx = tid; idx < 4 * 13; idx += blockDim.x) {
        int g = idx / 13, c = idx % 13;
        float4 w = make_float4(0.f, 0.f, 0.f, 0.f);
        float* wf = (float*)&w;
        for (int j = 0; j < 4; j++) {
            int k = c * 4 + j;
            if (k < H1) wf[j] = Wih2[g * H1 + k];
        }
        W2s[idx] = w;
    }
    for (int idx = tid; idx < 2 * 4 * 13; idx += blockDim.x)
        ((float4*)Hs)[idx] = make_float4(0.f, 0.f, 0.f, 0.f);
    __syncthreads();

    const ulonglong2* __restrict__ W1u = reinterpret_cast<const ulonglong2*>(W1s);

    const int lane = tid & 31;
    const int w    = tid >> 5;                    // warp in block
    const int warp = blockIdx.x * 2 + w;

    const int  uA  = lane;
    const bool hasB = (lane + 32) < H1;           // lanes 0..18
    const int  uB  = hasB ? (lane + 32) : H1;     // pad col 51 for 19..31
    const int  uBw = hasB ? (lane + 32) : 0;

    // ---- per-lane constants ----
    float WiA[4], WiB[4], bA[4], bB[4];
#pragma unroll
    for (int g = 0; g < 4; g++) {
        WiA[g] = Wih1[g * H1 + uA];
        bA[g]  = bih1[g * H1 + uA] + bhh1[g * H1 + uA];
        float wib = Wih1[g * H1 + uBw];
        float bb  = bih1[g * H1 + uBw] + bhh1[g * H1 + uBw];
        WiB[g] = hasB ? wib : 0.f;
        bB[g]  = hasB ? bb  : 0.f;
    }
    const ull WiAp0 = pack2(WiA[0], WiA[1]), WiAp1 = pack2(WiA[2], WiA[3]);
    const ull WiBp0 = pack2(WiB[0], WiB[1]), WiBp1 = pack2(WiB[2], WiB[3]);
    const ull bAp0  = pack2(bA[0],  bA[1]),  bAp1  = pack2(bA[2],  bA[3]);
    const ull bBp0  = pack2(bB[0],  bB[1]),  bBp1  = pack2(bB[2],  bB[3]);

    // LSTM2 lane mapping: lanes 16..31 mirror elems 0..3 (all lanes valid)
    const int e2 = (lane >> 2) & 3;
    const int g2 = lane & 3;
    const float W2h_l = Whh2[g2];
    const float b2_l  = bih2[g2] + bhh2[g2];

    // ---- state ----
    float hA[4] = {0.f, 0.f, 0.f, 0.f};
    float hB[4] = {0.f, 0.f, 0.f, 0.f};
    float cA[4] = {0.f, 0.f, 0.f, 0.f};
    float cB[4] = {0.f, 0.f, 0.f, 0.f};
    float h2v = 0.f, c2v = 0.f;          // per-group LSTM2 state (consistent
                                         // within each 4-lane group)

    const float* inp[4];
#pragma unroll
    for (int e = 0; e < 4; e++)
        inp[e] = input + (size_t)(warp * 4 + e) * T;
    // output writer lanes: 0,4,8,12 -> elems 0..3
    float* myout = ((lane & 3) == 0 && lane < 16)
                 ? out + (size_t)(warp * 4 + (lane >> 2)) * TF : nullptr;

#pragma unroll 1
    for (int t = 0; t <= TF; t++) {
        // ---- deferred LSTM2 for step t-1 (reads h1(t-1) from Hs) ----
        if (t > 0) {
            float acc0 = 0.f, acc1 = 0.f;
#pragma unroll
            for (int c = 0; c < 13; c++) {
                float4 hv = Hs[w][e2][c];
                float4 wv = W2s[g2 * 13 + c];
                acc0 = fmaf(hv.x, wv.x, fmaf(hv.y, wv.y, acc0));
                acc1 = fmaf(hv.z, wv.z, fmaf(hv.w, wv.w, acc1));
            }
            float pre = acc0 + acc1 + W2h_l * h2v + b2_l;
            const int base = lane & ~3;
            float pi = __shfl_sync(FULLMASK, pre, base + 0);
            float pf = __shfl_sync(FULLMASK, pre, base + 1);
            float pg = __shfl_sync(FULLMASK, pre, base + 2);
            float po = __shfl_sync(FULLMASK, pre, base + 3);
            float i2 = fsig(pi), f2 = fsig(pf), gg = ftanh(pg), o2 = fsig(po);
            c2v = f2 * c2v + i2 * gg;
            h2v = o2 * ftanh(c2v);
            if (myout) myout[t - 1] = h2v;
        }
        if (t == TF) break;

        // ---- LSTM1 input: data in main phase, own h2 in future phase ----
        float x[4];
        if (t < T) {
#pragma unroll
            for (int e = 0; e < 4; e++) x[e] = __ldg(inp[e] + t);
        } else {
#pragma unroll
            for (int e = 0; e < 4; e++)
                x[e] = __shfl_sync(FULLMASK, h2v, e << 2);
        }

        // ---- gate accumulators (packed pairs): bias + x*Wih ----
        ull aA0[4], aA1[4], aB0[4], aB1[4];
#pragma unroll
        for (int e = 0; e < 4; e++) {
            ull d = dup2(x[e]);
            FMA2(aA0[e], d, WiAp0, bAp0);
            FMA2(aA1[e], d, WiAp1, bAp1);
            FMA2(aB0[e], d, WiBp0, bBp0);
            FMA2(aB1[e], d, WiBp1, bBp1);
        }

        // ---- recurrent dot: 13 chunks x 4 k, h via broadcast LDS.128 ----
#pragma unroll
        for (int kc = 0; kc < 13; kc++) {
            float4 hv0 = Hs[w][0][kc];
            float4 hv1 = Hs[w][1][kc];
            float4 hv2 = Hs[w][2][kc];
            float4 hv3 = Hs[w][3][kc];
#pragma unroll
            for (int j = 0; j < 4; j++) {
                const int k = kc * 4 + j;
                const ulonglong2 wA = W1u[k * KP + uA];
                const ulonglong2 wB = W1u[k * KP + uB];
                float hk0 = (j == 0) ? hv0.x : (j == 1) ? hv0.y : (j == 2) ? hv0.z : hv0.w;
                float hk1 = (j == 0) ? hv1.x : (j == 1) ? hv1.y : (j == 2) ? hv1.z : hv1.w;
                float hk2 = (j == 0) ? hv2.x : (j == 1) ? hv2.y : (j == 2) ? hv2.z : hv2.w;
                float hk3 = (j == 0) ? hv3.x : (j == 1) ? hv3.y : (j == 2) ? hv3.z : hv3.w;
                ull d0 = dup2(hk0), d1 = dup2(hk1), d2 = dup2(hk2), d3 = dup2(hk3);
                FMA2(aA0[0], d0, wA.x, aA0[0]);
                FMA2(aA1[0], d0, wA.y, aA1[0]);
                FMA2(aB0[0], d0, wB.x, aB0[0]);
                FMA2(aB1[0], d0, wB.y, aB1[0]);
                FMA2(aA0[1], d1, wA.x, aA0[1]);
                FMA2(aA1[1], d1, wA.y, aA1[1]);
                FMA2(aB0[1], d1, wB.x, aB0[1]);
                FMA2(aB1[1], d1, wB.y, aB1[1]);
                FMA2(aA0[2], d2, wA.x, aA0[2]);
                FMA2(aA1[2], d2, wA.y, aA1[2]);
                FMA2(aB0[2], d2, wB.x, aB0[2]);
                FMA2(aB1[2], d2, wB.y, aB1[2]);
                FMA2(aA0[3], d3, wA.x, aA0[3]);
                FMA2(aA1[3], d3, wA.y, aA1[3]);
                FMA2(aB0[3], d3, wB.x, aB0[3]);
                FMA2(aB1[3], d3, wB.y, aB1[3]);
            }
        }

        // ---- LSTM1 activations + state update ----
#pragma unroll
        for (int e = 0; e < 4; e++) {
            float2 vA0 = unpack2(aA0[e]), vA1 = unpack2(aA1[e]);
            float2 vB0 = unpack2(aB0[e]), vB1 = unpack2(aB1[e]);
            {
                float i = fsig(vA0.x), f = fsig(vA0.y);
                float g = ftanh(vA1.x), o = fsig(vA1.y);
                cA[e] = f * cA[e] + i * g;
                hA[e] = o * ftanh(cA[e]);
            }
            {
                float i = fsig(vB0.x), f = fsig(vB0.y);
                float g = ftanh(vB1.x), o = fsig(vB1.y);
                cB[e] = f * cB[e] + i * g;
                hB[e] = o * ftanh(cB[e]);
            }
        }

        // ---- publish h(t) to shared (unit 51 stays 0 forever) ----
        __syncwarp();
#pragma unroll
        for (int e = 0; e < 4; e++) {
            float* hrow = (float*)&Hs[w][e][0];
            hrow[lane] = hA[e];
            if (hasB) hrow[lane + 32] = hB[e];
        }
        __syncwarp();
    }
}

extern "C" void kernel_launch(void* const* d_in, const int* in_sizes, int n_in,
                              void* d_out, int out_size) {
    const float* input = (const float*)d_in[0];
    const float* Wih1  = (const float*)d_in[1];
    const float* Whh1  = (const float*)d_in[2];
    const float* bih1  = (const float*)d_in[3];
    const float* bhh1  = (const float*)d_in[4];
    const float* Wih2  = (const float*)d_in[5];
    const float* Whh2  = (const float*)d_in[6];
    const float* bih2  = (const float*)d_in[7];
    const float* bhh2  = (const float*)d_in[8];
    float* out = (float*)d_out;

    const int B  = 2048;
    const int T  = in_sizes[0] / B;     // 1024
    const int TF = out_size / B;        // 1088

    // 2 warps/block, 4 batch elements/warp -> 8 batch/block -> 256 blocks
    lstm_seq_kernel<<<B / 8, 64>>>(input, Wih1, Whh1, bih1, bhh1,
                                   Wih2, Whh2, bih2, bhh2,
                                   out, T, TF);
}